// round 11
// baseline (speedup 1.0000x reference)
#include <cuda_runtime.h>
#include <cuda_bf16.h>
#include <cstdint>

// Problem constants
#define NN   4096
#define PP   32768
#define EE   4096
#define DD   128
#define RR   4
#define KK   16
#define NW   128       // 4096 bits / 32 words per adjacency row

// ---- K1 striping: group of 3 = 2 pack rows + 1 gather block; +1 tail ----
#define GRID_1  (2048 * 3 + 1)
// ---- K2 striping: group of 18 = 16 tri + 1 proj + 1 egemm ----
#define GRID_2  (256 * 18)

// ---------------- device scratch ----------------
__device__ unsigned g_bits  [NN * NW];
__device__ float    g_C     [NN];           // clustering coeff
__device__ float    g_invden[NN];           // 2 / (deg*(deg-1) or 1e-6)
__device__ float    g_proj  [NN * DD];
__device__ float    g_eps   [NN * DD];
__device__ float    g_hbar  [NN * RR * DD]; // [n][r*128+d]
__device__ float    g_alpha;

// ---------------- packed fp32x2 helpers (sm_100+) ----------------
__device__ __forceinline__ unsigned long long pk(float x, float y) {
    unsigned long long r;
    asm("mov.b64 %0, {%1, %2};" : "=l"(r) : "f"(x), "f"(y));
    return r;
}
__device__ __forceinline__ void upk(float& x, float& y, unsigned long long v) {
    asm("mov.b64 {%0, %1}, %2;" : "=f"(x), "=f"(y) : "l"(v));
}
__device__ __forceinline__ void ffma2(unsigned long long& d,
                                      unsigned long long a,
                                      unsigned long long b) {
    asm("fma.rn.f32x2 %0, %1, %2, %0;" : "+l"(d) : "l"(a), "l"(b));
}

// =======================================================================
// K1: pack | gather striped  [unchanged — measured near LTS cap]
// =======================================================================
__global__ void __launch_bounds__(256)
k_1(const int*   __restrict__ adj,
    const float* __restrict__ emb,
    const int*   __restrict__ nidx,
    const float* __restrict__ tev,
    const float* __restrict__ theta_p) {
    __shared__ int   sdeg[8];
    __shared__ float sw[8];

    int b    = blockIdx.x;
    int tid  = threadIdx.x;
    int lane = tid & 31, w = tid >> 5;

    if (b < 2048 * 3) {
        int r = b % 3, q = b / 3;
        if (r < 2) {
            int row = q * 2 + r;
            const int* a = adj + (size_t)row * NN;
            int v[16];
            #pragma unroll
            for (int i = 0; i < 16; i++)
                v[i] = a[(w * 16 + i) * 32 + lane];
            unsigned keep = 0;
            #pragma unroll
            for (int i = 0; i < 16; i++) {
                unsigned m = __ballot_sync(0xffffffffu, v[i] != 0);
                if (lane == i) keep = m;
            }
            if (lane < 16)
                g_bits[row * NW + w * 16 + lane] = keep;
            int dsum = (lane < 16) ? __popc(keep) : 0;
            #pragma unroll
            for (int o = 16; o; o >>= 1)
                dsum += __shfl_down_sync(0xffffffffu, dsum, o);
            if (lane == 0) sdeg[w] = dsum;
            __syncthreads();
            if (tid == 0) {
                int s = 0;
                #pragma unroll
                for (int i = 0; i < 8; i++) s += sdeg[i];
                float d   = (float)s;
                float den = d * (d - 1.0f);
                if (den == 0.0f) den = 1e-6f;
                g_invden[row] = 2.0f / den;
            }
        } else {
            int unit = q * 8 + w;
            const float4* e4 = (const float4*)emb;
            int nid = 0;
            if (lane < KK) nid = nidx[unit * KK + lane];
            float4 acc = make_float4(0.f, 0.f, 0.f, 0.f);
            #pragma unroll
            for (int k = 0; k < KK; k++) {
                int id = __shfl_sync(0xffffffffu, nid, k);
                float4 v = __ldg(&e4[id * 32 + lane]);
                acc.x += v.x; acc.y += v.y; acc.z += v.z; acc.w += v.w;
            }
            ((float4*)g_hbar)[unit * 32 + lane] =
                make_float4(acc.x * 0.0625f, acc.y * 0.0625f,
                            acc.z * 0.0625f, acc.w * 0.0625f);
        }
    } else {
        float th = theta_p[0];
        float s  = 0.f;
        for (int i = tid; i < EE; i += 256)
            s += expf(-th * (1.0f - tev[i]));
        #pragma unroll
        for (int o = 16; o; o >>= 1) s += __shfl_down_sync(0xffffffffu, s, o);
        if (lane == 0) sw[w] = s;
        __syncthreads();
        if (tid == 0) {
            float tot = 0.f;
            #pragma unroll
            for (int i = 0; i < 8; i++) tot += sw[i];
            g_alpha = tot;
        }
    }
}

// =======================================================================
// K2: tri (MLP-4) | proj (wt prefetch) | egemm (wt prefetch-8), striped
// =======================================================================
__global__ void __launch_bounds__(256)
k_2(const float* __restrict__ emb,
    const float* __restrict__ Wp,
    const int*   __restrict__ ntype,
    const float* __restrict__ Wb,
    const float* __restrict__ bb) {
    __shared__ __align__(16) char sm[33 * 1024];    // union
    __shared__ int   sty[16];
    __shared__ int   scnt;
    __shared__ int   swsum[8];

    int b    = blockIdx.x;
    int tid  = threadIdx.x;
    int lane = tid & 31, w = tid >> 5;
    int r    = b % 18, q = b / 18;

    if (r < 16) {
        // ---------- full-edge triangle scan, 4-deep j prefetch ----------
        unsigned* sri  = (unsigned*)sm;
        int*      list = (int*)(sm + 512);
        int i = q * 16 + r;
        if (tid == 0) scnt = 0;
        if (tid < NW) sri[tid] = g_bits[i * NW + tid];
        __syncthreads();
        if (tid < NW) {
            unsigned word = sri[tid];
            while (word) {
                int bit = __ffs(word) - 1;
                word &= word - 1;
                int pos = atomicAdd(&scnt, 1);
                list[pos] = tid * 32 + bit;
            }
        }
        __syncthreads();
        int cnt = scnt;
        uint4 ri = ((const uint4*)sri)[lane];
        int my = 0;
        int idx = w;
        for (; idx + 24 < cnt; idx += 32) {           // 4 rows in flight
            int j0 = list[idx],      j1 = list[idx + 8];
            int j2 = list[idx + 16], j3 = list[idx + 24];
            uint4 x0 = ((const uint4*)&g_bits[j0 * NW])[lane];
            uint4 x1 = ((const uint4*)&g_bits[j1 * NW])[lane];
            uint4 x2 = ((const uint4*)&g_bits[j2 * NW])[lane];
            uint4 x3 = ((const uint4*)&g_bits[j3 * NW])[lane];
            my += __popc(x0.x & ri.x) + __popc(x0.y & ri.y)
                + __popc(x0.z & ri.z) + __popc(x0.w & ri.w);
            my += __popc(x1.x & ri.x) + __popc(x1.y & ri.y)
                + __popc(x1.z & ri.z) + __popc(x1.w & ri.w);
            my += __popc(x2.x & ri.x) + __popc(x2.y & ri.y)
                + __popc(x2.z & ri.z) + __popc(x2.w & ri.w);
            my += __popc(x3.x & ri.x) + __popc(x3.y & ri.y)
                + __popc(x3.z & ri.z) + __popc(x3.w & ri.w);
        }
        for (; idx < cnt; idx += 8) {
            int j0 = list[idx];
            uint4 x0 = ((const uint4*)&g_bits[j0 * NW])[lane];
            my += __popc(x0.x & ri.x) + __popc(x0.y & ri.y)
                + __popc(x0.z & ri.z) + __popc(x0.w & ri.w);
        }
        #pragma unroll
        for (int o = 16; o; o >>= 1) my += __shfl_down_sync(0xffffffffu, my, o);
        if (lane == 0) swsum[w] = my;
        __syncthreads();
        if (tid == 0) {
            int tot = 0;
            #pragma unroll
            for (int k = 0; k < 8; k++) tot += swsum[k];
            g_C[i] = (float)tot * g_invden[i];
        }
    } else if (r == 16) {
        // ---------- type-selected projection, 16-node, 2-d weight prefetch ----------
        float* semb = (float*)sm;                       // [d][n] stride 20
        float* sred = (float*)(sm + 10 * 1024 + 256);
        int n0 = q * 16;
        int e  = tid & 127, g = tid >> 7;
        for (int idx = tid; idx < 16 * DD; idx += 256) {
            int d = idx & 127, n = idx >> 7;
            semb[d * 20 + n] = emb[(n0 + n) * DD + d];
        }
        if (tid < 16) sty[tid] = ntype[n0 + tid];
        __syncthreads();
        int ty[16];
        #pragma unroll
        for (int n = 0; n < 16; n++) ty[n] = sty[n];
        float acc[16];
        #pragma unroll
        for (int n = 0; n < 16; n++) acc[n] = 0.f;
        int dbase = g * 64;
        for (int i = 0; i < 64; i += 2) {              // 6 weight LDGs in flight
            int da = dbase + i, db = dbase + i + 1;
            float w0a = Wp[(0 * DD + da) * DD + e];
            float w1a = Wp[(1 * DD + da) * DD + e];
            float w2a = Wp[(2 * DD + da) * DD + e];
            float w0b = Wp[(0 * DD + db) * DD + e];
            float w1b = Wp[(1 * DD + db) * DD + e];
            float w2b = Wp[(2 * DD + db) * DD + e];
            const float4* rowa = (const float4*)&semb[da * 20];
            const float4* rowb = (const float4*)&semb[db * 20];
            #pragma unroll
            for (int p = 0; p < 4; p++) {
                float4 va = rowa[p];
                { int n=4*p+0; float wv=(ty[n]==0)?w0a:((ty[n]==1)?w1a:w2a); acc[n]+=va.x*wv; }
                { int n=4*p+1; float wv=(ty[n]==0)?w0a:((ty[n]==1)?w1a:w2a); acc[n]+=va.y*wv; }
                { int n=4*p+2; float wv=(ty[n]==0)?w0a:((ty[n]==1)?w1a:w2a); acc[n]+=va.z*wv; }
                { int n=4*p+3; float wv=(ty[n]==0)?w0a:((ty[n]==1)?w1a:w2a); acc[n]+=va.w*wv; }
            }
            #pragma unroll
            for (int p = 0; p < 4; p++) {
                float4 vb = rowb[p];
                { int n=4*p+0; float wv=(ty[n]==0)?w0b:((ty[n]==1)?w1b:w2b); acc[n]+=vb.x*wv; }
                { int n=4*p+1; float wv=(ty[n]==0)?w0b:((ty[n]==1)?w1b:w2b); acc[n]+=vb.y*wv; }
                { int n=4*p+2; float wv=(ty[n]==0)?w0b:((ty[n]==1)?w1b:w2b); acc[n]+=vb.z*wv; }
                { int n=4*p+3; float wv=(ty[n]==0)?w0b:((ty[n]==1)?w1b:w2b); acc[n]+=vb.w*wv; }
            }
        }
        if (g == 1) {
            #pragma unroll
            for (int n = 0; n < 16; n++) sred[n * DD + e] = acc[n];
        }
        __syncthreads();
        if (g == 0) {
            #pragma unroll
            for (int n = 0; n < 16; n++)
                g_proj[(n0 + n) * DD + e] = acc[n] + sred[n * DD + e];
        }
    } else {
        // ---------- eps GEMM, 16-node, f32x2, 8-deep weight prefetch ----------
        float* sbuf = (float*)sm;                       // [rd][n] 512*16
        int n0 = q * 16;
        int e  = tid & 127, g = tid >> 7;
        for (int idx = tid; idx < 16 * 512; idx += 256) {
            int n = idx >> 9, rd = idx & 511;
            sbuf[rd * 16 + n] = g_hbar[(n0 + n) * 512 + rd];
        }
        __syncthreads();
        unsigned long long acc[8];
        #pragma unroll
        for (int p = 0; p < 8; p++) acc[p] = 0ull;
        int rdbase = g * 256;
        for (int i2 = 0; i2 < 256; i2 += 8) {
            float wv[8];
            #pragma unroll
            for (int t = 0; t < 8; t++)
                wv[t] = Wb[(rdbase + i2 + t) * DD + e];  // 8 LDG in flight
            #pragma unroll
            for (int t = 0; t < 8; t++) {
                unsigned long long w2 = pk(wv[t], wv[t]);
                const ulonglong2* row =
                    (const ulonglong2*)&sbuf[(rdbase + i2 + t) * 16];
                ulonglong2 v0 = row[0];
                ulonglong2 v1 = row[1];
                ffma2(acc[0], v0.x, w2);
                ffma2(acc[1], v0.y, w2);
                ffma2(acc[2], v1.x, w2);
                ffma2(acc[3], v1.y, w2);
                ulonglong2 v2 = row[2];
                ulonglong2 v3 = row[3];
                ffma2(acc[4], v2.x, w2);
                ffma2(acc[5], v2.y, w2);
                ffma2(acc[6], v3.x, w2);
                ffma2(acc[7], v3.y, w2);
            }
        }
        float a[16];
        #pragma unroll
        for (int p = 0; p < 8; p++) upk(a[2 * p], a[2 * p + 1], acc[p]);
        __syncthreads();
        if (g == 1) {
            #pragma unroll
            for (int n = 0; n < 16; n++) sbuf[n * DD + e] = a[n];
        }
        __syncthreads();
        if (g == 0) {
            float bsum = bb[e] + bb[DD + e] + bb[2 * DD + e] + bb[3 * DD + e];
            #pragma unroll
            for (int n = 0; n < 16; n++) {
                float t = a[n] + sbuf[n * DD + e];
                float h = (t + bsum) * 0.25f;
                g_eps[(n0 + n) * DD + e] = 1.0f / (1.0f + expf(-h));
            }
        }
    }
}

// =======================================================================
// K3: per-pair score (warp per pair), front-batched loads
// =======================================================================
__global__ void __launch_bounds__(256)
k_pairs(const int*   __restrict__ pairs,
        const float* __restrict__ emb,
        const float* __restrict__ q1p,
        const float* __restrict__ q2p,
        float*       __restrict__ out) {
    int gw   = (blockIdx.x * blockDim.x + threadIdx.x) >> 5;
    int lane = threadIdx.x & 31;
    if (gw >= PP) return;
    int pm = pairs[gw * 2 + 0];
    int pn = pairs[gw * 2 + 1];

    // front-batch: 8 independent LDG.128 before any math
    float4 a  = ((const float4*)&g_proj[pm * DD])[lane];
    float4 b  = ((const float4*)&g_proj[pn * DD])[lane];
    float4 ea = ((const float4*)&emb[pm * DD])[lane];
    float4 eb = ((const float4*)&emb[pn * DD])[lane];
    float4 pa = ((const float4*)&g_eps[pm * DD])[lane];
    float4 pb = ((const float4*)&g_eps[pn * DD])[lane];
    uint4  bm = ((const uint4*)&g_bits[pm * NW])[lane];
    uint4  bn = ((const uint4*)&g_bits[pn * NW])[lane];

    float dx0 = a.x - b.x, dx1 = a.y - b.y, dx2 = a.z - b.z, dx3 = a.w - b.w;
    float s1  = dx0*dx0 + dx1*dx1 + dx2*dx2 + dx3*dx3;

    float e0 = ea.x - eb.x, e1 = ea.y - eb.y, e2 = ea.z - eb.z, e3 = ea.w - eb.w;
    float s2 = e0*e0 + e1*e1 + e2*e2 + e3*e3;

    float s3 = pa.x*pb.x + pa.y*pb.y + pa.z*pb.z + pa.w*pb.w;

    float cs = 0.f;
    {
        unsigned ws[4] = { bm.x & bn.x, bm.y & bn.y, bm.z & bn.z, bm.w & bn.w };
        #pragma unroll
        for (int c = 0; c < 4; c++) {
            unsigned word = ws[c];
            int j0 = (lane * 4 + c) * 32;
            while (word) {
                int bpos = __ffs(word) - 1;
                word &= word - 1;
                cs += g_C[j0 + bpos];
            }
        }
    }

    #pragma unroll
    for (int o = 16; o; o >>= 1) {
        s1 += __shfl_xor_sync(0xffffffffu, s1, o);
        s2 += __shfl_xor_sync(0xffffffffu, s2, o);
        s3 += __shfl_xor_sync(0xffffffffu, s3, o);
        cs += __shfl_xor_sync(0xffffffffu, cs, o);
    }

    if (lane == 0) {
        float gamma = -sqrtf(s1);
        float g     = -s2;
        float lamb  = gamma + g_alpha + cs * g + s3 * (1.0f / (float)DD);
        float lam   = expf(lamb);
        float z     = q1p[0] * lam + q2p[0];
        out[gw] = 1.0f / (1.0f + expf(-z));
    }
}

// ---------------- launcher ----------------
extern "C" void kernel_launch(void* const* d_in, const int* in_sizes, int n_in,
                              void* d_out, int out_size) {
    const int*   pairs   = (const int*)  d_in[0];
    const int*   adj     = (const int*)  d_in[1];
    const int*   nidx    = (const int*)  d_in[2];
    const int*   ntype   = (const int*)  d_in[3];
    const float* tev     = (const float*)d_in[4];
    const float* emb     = (const float*)d_in[5];
    const float* Wp      = (const float*)d_in[6];
    const float* Wb      = (const float*)d_in[7];
    const float* bb      = (const float*)d_in[8];
    const float* theta_p = (const float*)d_in[9];
    const float* q1p     = (const float*)d_in[10];
    const float* q2p     = (const float*)d_in[11];
    float*       out     = (float*)d_out;

    k_1    <<<GRID_1, 256>>>(adj, emb, nidx, tev, theta_p);
    k_2    <<<GRID_2, 256>>>(emb, Wp, ntype, Wb, bb);
    k_pairs<<<PP / 8, 256>>>(pairs, emb, q1p, q2p, out);
}

// round 12
// speedup vs baseline: 1.0277x; 1.0277x over previous
#include <cuda_runtime.h>
#include <cuda_bf16.h>
#include <cstdint>

// Problem constants
#define NN   4096
#define PP   32768
#define EE   4096
#define DD   128
#define RR   4
#define KK   16
#define NW   128       // 4096 bits / 32 words per adjacency row

// ---- K1 striping: group of 3 = 2 pack rows + 1 gather block; +1 tail ----
#define GRID_1  (2048 * 3 + 1)

// ---------------- device scratch ----------------
__device__ unsigned g_bits  [NN * NW];
__device__ float    g_C     [NN];           // clustering coeff
__device__ float    g_invden[NN];           // 2 / (deg*(deg-1) or 1e-6)
__device__ float    g_proj  [NN * DD];
__device__ float    g_eps   [NN * DD];
__device__ float    g_hbar  [NN * RR * DD]; // [n][r*128+d]
__device__ float    g_alpha;

// ---------------- packed fp32x2 helpers (sm_100+) ----------------
__device__ __forceinline__ unsigned long long pk(float x, float y) {
    unsigned long long r;
    asm("mov.b64 %0, {%1, %2};" : "=l"(r) : "f"(x), "f"(y));
    return r;
}
__device__ __forceinline__ void upk(float& x, float& y, unsigned long long v) {
    asm("mov.b64 {%0, %1}, %2;" : "=f"(x), "=f"(y) : "l"(v));
}
__device__ __forceinline__ void ffma2(unsigned long long& d,
                                      unsigned long long a,
                                      unsigned long long b) {
    asm("fma.rn.f32x2 %0, %1, %2, %0;" : "+l"(d) : "l"(a), "l"(b));
}

// =======================================================================
// K1: pack | gather | alpha striped  [unchanged — at LTS saturation]
// =======================================================================
__global__ void __launch_bounds__(256)
k_1(const int*   __restrict__ adj,
    const float* __restrict__ emb,
    const int*   __restrict__ nidx,
    const float* __restrict__ tev,
    const float* __restrict__ theta_p) {
    __shared__ int   sdeg[8];
    __shared__ float sw[8];

    int b    = blockIdx.x;
    int tid  = threadIdx.x;
    int lane = tid & 31, w = tid >> 5;

    if (b < 2048 * 3) {
        int r = b % 3, q = b / 3;
        if (r < 2) {
            int row = q * 2 + r;
            const int* a = adj + (size_t)row * NN;
            int v[16];
            #pragma unroll
            for (int i = 0; i < 16; i++)
                v[i] = a[(w * 16 + i) * 32 + lane];
            unsigned keep = 0;
            #pragma unroll
            for (int i = 0; i < 16; i++) {
                unsigned m = __ballot_sync(0xffffffffu, v[i] != 0);
                if (lane == i) keep = m;
            }
            if (lane < 16)
                g_bits[row * NW + w * 16 + lane] = keep;
            int dsum = (lane < 16) ? __popc(keep) : 0;
            #pragma unroll
            for (int o = 16; o; o >>= 1)
                dsum += __shfl_down_sync(0xffffffffu, dsum, o);
            if (lane == 0) sdeg[w] = dsum;
            __syncthreads();
            if (tid == 0) {
                int s = 0;
                #pragma unroll
                for (int i = 0; i < 8; i++) s += sdeg[i];
                float d   = (float)s;
                float den = d * (d - 1.0f);
                if (den == 0.0f) den = 1e-6f;
                g_invden[row] = 2.0f / den;
            }
        } else {
            int unit = q * 8 + w;
            const float4* e4 = (const float4*)emb;
            int nid = 0;
            if (lane < KK) nid = nidx[unit * KK + lane];
            float4 acc = make_float4(0.f, 0.f, 0.f, 0.f);
            #pragma unroll
            for (int k = 0; k < KK; k++) {
                int id = __shfl_sync(0xffffffffu, nid, k);
                float4 v = __ldg(&e4[id * 32 + lane]);
                acc.x += v.x; acc.y += v.y; acc.z += v.z; acc.w += v.w;
            }
            ((float4*)g_hbar)[unit * 32 + lane] =
                make_float4(acc.x * 0.0625f, acc.y * 0.0625f,
                            acc.z * 0.0625f, acc.w * 0.0625f);
        }
    } else {
        float th = theta_p[0];
        float s  = 0.f;
        for (int i = tid; i < EE; i += 256)
            s += expf(-th * (1.0f - tev[i]));
        #pragma unroll
        for (int o = 16; o; o >>= 1) s += __shfl_down_sync(0xffffffffu, s, o);
        if (lane == 0) sw[w] = s;
        __syncthreads();
        if (tid == 0) {
            float tot = 0.f;
            #pragma unroll
            for (int i = 0; i < 8; i++) tot += sw[i];
            g_alpha = tot;
        }
    }
}

// =======================================================================
// K2a: tri — LEAN standalone kernel (low regs, 2KB smem, max occupancy)
//      ballot-prefix list build (no smem atomics), 4-deep j prefetch
// =======================================================================
__global__ void __launch_bounds__(256)
k_tri() {
    __shared__ __align__(16) unsigned sri[NW];
    __shared__ int  list[192];
    __shared__ int  warpsum[4], warpbase[4];
    __shared__ int  scnt;
    __shared__ int  swsum[8];

    int i    = blockIdx.x;
    int tid  = threadIdx.x;
    int lane = tid & 31, w = tid >> 5;

    if (tid < NW) sri[tid] = g_bits[i * NW + tid];
    __syncthreads();

    // ---- ballot-prefix compact neighbor list (no atomics) ----
    unsigned word = 0; int c = 0, x = 0;
    if (tid < NW) {
        word = sri[tid];
        c = __popc(word);
        x = c;
        #pragma unroll
        for (int o = 1; o < 32; o <<= 1) {
            int y = __shfl_up_sync(0xffffffffu, x, o);
            if (lane >= o) x += y;
        }
        if (lane == 31) warpsum[w] = x;
    }
    __syncthreads();
    if (tid == 0) {
        int s = 0;
        #pragma unroll
        for (int k = 0; k < 4; k++) { int t = warpsum[k]; warpbase[k] = s; s += t; }
        scnt = s;
    }
    __syncthreads();
    if (tid < NW) {
        int base = warpbase[w] + x - c;        // exclusive prefix
        while (word) {
            int bit = __ffs(word) - 1;
            word &= word - 1;
            list[base++] = tid * 32 + bit;
        }
    }
    __syncthreads();

    int cnt = scnt;
    uint4 ri = ((const uint4*)sri)[lane];
    int my = 0;
    int idx = w;
    for (; idx + 24 < cnt; idx += 32) {        // 4 j-rows in flight
        int j0 = list[idx],      j1 = list[idx + 8];
        int j2 = list[idx + 16], j3 = list[idx + 24];
        uint4 x0 = ((const uint4*)&g_bits[j0 * NW])[lane];
        uint4 x1 = ((const uint4*)&g_bits[j1 * NW])[lane];
        uint4 x2 = ((const uint4*)&g_bits[j2 * NW])[lane];
        uint4 x3 = ((const uint4*)&g_bits[j3 * NW])[lane];
        my += __popc(x0.x & ri.x) + __popc(x0.y & ri.y)
            + __popc(x0.z & ri.z) + __popc(x0.w & ri.w);
        my += __popc(x1.x & ri.x) + __popc(x1.y & ri.y)
            + __popc(x1.z & ri.z) + __popc(x1.w & ri.w);
        my += __popc(x2.x & ri.x) + __popc(x2.y & ri.y)
            + __popc(x2.z & ri.z) + __popc(x2.w & ri.w);
        my += __popc(x3.x & ri.x) + __popc(x3.y & ri.y)
            + __popc(x3.z & ri.z) + __popc(x3.w & ri.w);
    }
    for (; idx < cnt; idx += 8) {
        int j0 = list[idx];
        uint4 x0 = ((const uint4*)&g_bits[j0 * NW])[lane];
        my += __popc(x0.x & ri.x) + __popc(x0.y & ri.y)
            + __popc(x0.z & ri.z) + __popc(x0.w & ri.w);
    }
    #pragma unroll
    for (int o = 16; o; o >>= 1) my += __shfl_down_sync(0xffffffffu, my, o);
    if (lane == 0) swsum[w] = my;
    __syncthreads();
    if (tid == 0) {
        int tot = 0;
        #pragma unroll
        for (int k = 0; k < 8; k++) tot += swsum[k];
        g_C[i] = (float)tot * g_invden[i];
    }
}

// =======================================================================
// K2b: proj | egemm striped 1:1 (both fat-FMA roles, matched regs)
// =======================================================================
__global__ void __launch_bounds__(256)
k_pe(const float* __restrict__ emb,
     const float* __restrict__ Wp,
     const int*   __restrict__ ntype,
     const float* __restrict__ Wb,
     const float* __restrict__ bb) {
    __shared__ __align__(16) char sm[33 * 1024];    // union
    __shared__ int sty[16];

    int b   = blockIdx.x;
    int tid = threadIdx.x;
    int r   = b & 1, q = b >> 1;

    if (r == 0) {
        // ---------- type-selected projection, 16-node, 2-d weight prefetch ----------
        float* semb = (float*)sm;                       // [d][n] stride 20
        float* sred = (float*)(sm + 10 * 1024 + 256);
        int n0 = q * 16;
        int e  = tid & 127, g = tid >> 7;
        for (int idx = tid; idx < 16 * DD; idx += 256) {
            int d = idx & 127, n = idx >> 7;
            semb[d * 20 + n] = emb[(n0 + n) * DD + d];
        }
        if (tid < 16) sty[tid] = ntype[n0 + tid];
        __syncthreads();
        int ty[16];
        #pragma unroll
        for (int n = 0; n < 16; n++) ty[n] = sty[n];
        float acc[16];
        #pragma unroll
        for (int n = 0; n < 16; n++) acc[n] = 0.f;
        int dbase = g * 64;
        for (int i = 0; i < 64; i += 2) {
            int da = dbase + i, db = dbase + i + 1;
            float w0a = Wp[(0 * DD + da) * DD + e];
            float w1a = Wp[(1 * DD + da) * DD + e];
            float w2a = Wp[(2 * DD + da) * DD + e];
            float w0b = Wp[(0 * DD + db) * DD + e];
            float w1b = Wp[(1 * DD + db) * DD + e];
            float w2b = Wp[(2 * DD + db) * DD + e];
            const float4* rowa = (const float4*)&semb[da * 20];
            const float4* rowb = (const float4*)&semb[db * 20];
            #pragma unroll
            for (int p = 0; p < 4; p++) {
                float4 va = rowa[p];
                { int n=4*p+0; float wv=(ty[n]==0)?w0a:((ty[n]==1)?w1a:w2a); acc[n]+=va.x*wv; }
                { int n=4*p+1; float wv=(ty[n]==0)?w0a:((ty[n]==1)?w1a:w2a); acc[n]+=va.y*wv; }
                { int n=4*p+2; float wv=(ty[n]==0)?w0a:((ty[n]==1)?w1a:w2a); acc[n]+=va.z*wv; }
                { int n=4*p+3; float wv=(ty[n]==0)?w0a:((ty[n]==1)?w1a:w2a); acc[n]+=va.w*wv; }
            }
            #pragma unroll
            for (int p = 0; p < 4; p++) {
                float4 vb = rowb[p];
                { int n=4*p+0; float wv=(ty[n]==0)?w0b:((ty[n]==1)?w1b:w2b); acc[n]+=vb.x*wv; }
                { int n=4*p+1; float wv=(ty[n]==0)?w0b:((ty[n]==1)?w1b:w2b); acc[n]+=vb.y*wv; }
                { int n=4*p+2; float wv=(ty[n]==0)?w0b:((ty[n]==1)?w1b:w2b); acc[n]+=vb.z*wv; }
                { int n=4*p+3; float wv=(ty[n]==0)?w0b:((ty[n]==1)?w1b:w2b); acc[n]+=vb.w*wv; }
            }
        }
        if (g == 1) {
            #pragma unroll
            for (int n = 0; n < 16; n++) sred[n * DD + e] = acc[n];
        }
        __syncthreads();
        if (g == 0) {
            #pragma unroll
            for (int n = 0; n < 16; n++)
                g_proj[(n0 + n) * DD + e] = acc[n] + sred[n * DD + e];
        }
    } else {
        // ---------- eps GEMM, 16-node, f32x2, 8-deep weight prefetch ----------
        float* sbuf = (float*)sm;                       // [rd][n] 512*16
        int n0 = q * 16;
        int e  = tid & 127, g = tid >> 7;
        for (int idx = tid; idx < 16 * 512; idx += 256) {
            int n = idx >> 9, rd = idx & 511;
            sbuf[rd * 16 + n] = g_hbar[(n0 + n) * 512 + rd];
        }
        __syncthreads();
        unsigned long long acc[8];
        #pragma unroll
        for (int p = 0; p < 8; p++) acc[p] = 0ull;
        int rdbase = g * 256;
        for (int i2 = 0; i2 < 256; i2 += 8) {
            float wv[8];
            #pragma unroll
            for (int t = 0; t < 8; t++)
                wv[t] = Wb[(rdbase + i2 + t) * DD + e];
            #pragma unroll
            for (int t = 0; t < 8; t++) {
                unsigned long long w2 = pk(wv[t], wv[t]);
                const ulonglong2* row =
                    (const ulonglong2*)&sbuf[(rdbase + i2 + t) * 16];
                ulonglong2 v0 = row[0];
                ulonglong2 v1 = row[1];
                ffma2(acc[0], v0.x, w2);
                ffma2(acc[1], v0.y, w2);
                ffma2(acc[2], v1.x, w2);
                ffma2(acc[3], v1.y, w2);
                ulonglong2 v2 = row[2];
                ulonglong2 v3 = row[3];
                ffma2(acc[4], v2.x, w2);
                ffma2(acc[5], v2.y, w2);
                ffma2(acc[6], v3.x, w2);
                ffma2(acc[7], v3.y, w2);
            }
        }
        float a[16];
        #pragma unroll
        for (int p = 0; p < 8; p++) upk(a[2 * p], a[2 * p + 1], acc[p]);
        __syncthreads();
        if (g == 1) {
            #pragma unroll
            for (int n = 0; n < 16; n++) sbuf[n * DD + e] = a[n];
        }
        __syncthreads();
        if (g == 0) {
            float bsum = bb[e] + bb[DD + e] + bb[2 * DD + e] + bb[3 * DD + e];
            #pragma unroll
            for (int n = 0; n < 16; n++) {
                float t = a[n] + sbuf[n * DD + e];
                float h = (t + bsum) * 0.25f;
                g_eps[(n0 + n) * DD + e] = 1.0f / (1.0f + expf(-h));
            }
        }
    }
}

// =======================================================================
// K3: per-pair score (warp per pair), front-batched loads
// =======================================================================
__global__ void __launch_bounds__(256)
k_pairs(const int*   __restrict__ pairs,
        const float* __restrict__ emb,
        const float* __restrict__ q1p,
        const float* __restrict__ q2p,
        float*       __restrict__ out) {
    int gw   = (blockIdx.x * blockDim.x + threadIdx.x) >> 5;
    int lane = threadIdx.x & 31;
    if (gw >= PP) return;
    int pm = pairs[gw * 2 + 0];
    int pn = pairs[gw * 2 + 1];

    float4 a  = ((const float4*)&g_proj[pm * DD])[lane];
    float4 b  = ((const float4*)&g_proj[pn * DD])[lane];
    float4 ea = ((const float4*)&emb[pm * DD])[lane];
    float4 eb = ((const float4*)&emb[pn * DD])[lane];
    float4 pa = ((const float4*)&g_eps[pm * DD])[lane];
    float4 pb = ((const float4*)&g_eps[pn * DD])[lane];
    uint4  bm = ((const uint4*)&g_bits[pm * NW])[lane];
    uint4  bn = ((const uint4*)&g_bits[pn * NW])[lane];

    float dx0 = a.x - b.x, dx1 = a.y - b.y, dx2 = a.z - b.z, dx3 = a.w - b.w;
    float s1  = dx0*dx0 + dx1*dx1 + dx2*dx2 + dx3*dx3;

    float e0 = ea.x - eb.x, e1 = ea.y - eb.y, e2 = ea.z - eb.z, e3 = ea.w - eb.w;
    float s2 = e0*e0 + e1*e1 + e2*e2 + e3*e3;

    float s3 = pa.x*pb.x + pa.y*pb.y + pa.z*pb.z + pa.w*pb.w;

    float cs = 0.f;
    {
        unsigned ws[4] = { bm.x & bn.x, bm.y & bn.y, bm.z & bn.z, bm.w & bn.w };
        #pragma unroll
        for (int c = 0; c < 4; c++) {
            unsigned word = ws[c];
            int j0 = (lane * 4 + c) * 32;
            while (word) {
                int bpos = __ffs(word) - 1;
                word &= word - 1;
                cs += g_C[j0 + bpos];
            }
        }
    }

    #pragma unroll
    for (int o = 16; o; o >>= 1) {
        s1 += __shfl_xor_sync(0xffffffffu, s1, o);
        s2 += __shfl_xor_sync(0xffffffffu, s2, o);
        s3 += __shfl_xor_sync(0xffffffffu, s3, o);
        cs += __shfl_xor_sync(0xffffffffu, cs, o);
    }

    if (lane == 0) {
        float gamma = -sqrtf(s1);
        float g     = -s2;
        float lamb  = gamma + g_alpha + cs * g + s3 * (1.0f / (float)DD);
        float lam   = expf(lamb);
        float z     = q1p[0] * lam + q2p[0];
        out[gw] = 1.0f / (1.0f + expf(-z));
    }
}

// ---------------- launcher ----------------
extern "C" void kernel_launch(void* const* d_in, const int* in_sizes, int n_in,
                              void* d_out, int out_size) {
    const int*   pairs   = (const int*)  d_in[0];
    const int*   adj     = (const int*)  d_in[1];
    const int*   nidx    = (const int*)  d_in[2];
    const int*   ntype   = (const int*)  d_in[3];
    const float* tev     = (const float*)d_in[4];
    const float* emb     = (const float*)d_in[5];
    const float* Wp      = (const float*)d_in[6];
    const float* Wb      = (const float*)d_in[7];
    const float* bb      = (const float*)d_in[8];
    const float* theta_p = (const float*)d_in[9];
    const float* q1p     = (const float*)d_in[10];
    const float* q2p     = (const float*)d_in[11];
    float*       out     = (float*)d_out;

    k_1    <<<GRID_1, 256>>>(adj, emb, nidx, tev, theta_p);
    k_tri  <<<NN, 256>>>();
    k_pe   <<<512, 256>>>(emb, Wp, ntype, Wb, bb);
    k_pairs<<<PP / 8, 256>>>(pairs, emb, q1p, q2p, out);
}